// round 5
// baseline (speedup 1.0000x reference)
#include <cuda_runtime.h>
#include <cuda_bf16.h>
#include <cstdint>

// ---------------------------------------------------------------------------
// Problem constants: b=4, n=4096, D=512, H=8, dh=64, M=256, l=16, 6 iters,
// conv k=33, eps=1e-5
// ---------------------------------------------------------------------------
#define NB   (4*4096*512)
#define MM   (32*256*256)
#define MD   (32*256*64)

__device__ float g_xn[NB];
__device__ float g_q[NB];
__device__ float g_k[NB];
__device__ float g_v[NB];
__device__ float g_ql[MD];
__device__ float g_kl[MD];
__device__ float g_a2[MM];
__device__ float g_z0[MM];
__device__ float g_z1[MM];
__device__ float g_t1[MM];
__device__ float g_t2[MM];
__device__ float g_t3[MM];
__device__ float g_w[MD];
__device__ float g_w2[MD];
__device__ float g_attn[NB];
__device__ float g_attn2[NB];
__device__ float g_red[2];

__device__ __forceinline__ float f2tf(float x) {
    uint32_t u;
    asm("cvt.rna.tf32.f32 %0, %1;" : "=r"(u) : "f"(x));
    return __uint_as_float(u);
}

// ---------------------------------------------------------------------------
// LayerNorm
// ---------------------------------------------------------------------------
__global__ void ln_kernel(const float* __restrict__ x, const float* __restrict__ w,
                          const float* __restrict__ bb, float* __restrict__ out) {
    int row = blockIdx.x;
    const float* xr = x + (size_t)row * 512;
    float* orow = out + (size_t)row * 512;
    int t = threadIdx.x;
    float v[4];
    float s = 0.f;
#pragma unroll
    for (int i = 0; i < 4; i++) { v[i] = xr[t + 128*i]; s += v[i]; }
#pragma unroll
    for (int o = 16; o; o >>= 1) s += __shfl_xor_sync(0xffffffffu, s, o);
    __shared__ float red[4];
    if ((t & 31) == 0) red[t >> 5] = s;
    __syncthreads();
    float mean = (red[0]+red[1]+red[2]+red[3]) * (1.f/512.f);
    float vs = 0.f;
#pragma unroll
    for (int i = 0; i < 4; i++) { float d = v[i]-mean; vs += d*d; }
#pragma unroll
    for (int o = 16; o; o >>= 1) vs += __shfl_xor_sync(0xffffffffu, vs, o);
    __syncthreads();
    if ((t & 31) == 0) red[t >> 5] = vs;
    __syncthreads();
    float var = (red[0]+red[1]+red[2]+red[3]) * (1.f/512.f);
    float rstd = rsqrtf(var + 1e-5f);
#pragma unroll
    for (int i = 0; i < 4; i++) {
        int c = t + 128*i;
        orow[c] = (v[i]-mean)*rstd*w[c] + bb[c];
    }
}

// ---------------------------------------------------------------------------
// TF32 GEMM, BIG variant: block 128x256, BK=16, 8 warps, warp tile 64x64.
// Higher smem intensity (A shared 4-way->2-way redundancy removed).
// Dynamic smem: A[2][128*20] + B[2][16*264] = 54272 B.
// EPI 0: QKV scatter. EPI 1: bias + residual add.
// ---------------------------------------------------------------------------
template<int EPI, int LDA, int LDB, int KD>
__global__ __launch_bounds__(256, 1) void mma_gemm_big(
        const float* __restrict__ A, const float* __restrict__ B,
        float* __restrict__ C0, float* __restrict__ C1, float* __restrict__ C2,
        const float* __restrict__ e0, const float* __restrict__ e1) {
    extern __shared__ float smx[];
    float* AsmB = smx;           // 2 x 2560
    float* BsmB = smx + 5120;    // 2 x 4224
    int tid = threadIdx.x;
    int lane = tid & 31, wid = tid >> 5;
    int wm = wid & 1, wn = wid >> 1;          // wn in 0..3
    int g = lane >> 2, t4 = lane & 3;
    int row0 = blockIdx.y * 128, col0 = blockIdx.x * 256;

    int arow = tid >> 1, akq = (tid & 1) * 8;
    int bkr = tid >> 4, bnc = (tid & 15) * 16;

    // stage iteration 0
    {
        const float* ap = A + (size_t)(row0 + arow) * LDA + akq;
        float4 a0 = *(const float4*)ap;
        float4 a1 = *(const float4*)(ap + 4);
        float* as = &AsmB[arow*20 + akq];
        as[0]=f2tf(a0.x); as[1]=f2tf(a0.y); as[2]=f2tf(a0.z); as[3]=f2tf(a0.w);
        as[4]=f2tf(a1.x); as[5]=f2tf(a1.y); as[6]=f2tf(a1.z); as[7]=f2tf(a1.w);
        const float* bp = B + (size_t)bkr * LDB + col0 + bnc;
        float* bs = &BsmB[bkr*264 + bnc];
#pragma unroll
        for (int q4 = 0; q4 < 4; q4++) {
            float4 bv = *(const float4*)(bp + q4*4);
            bs[q4*4+0]=f2tf(bv.x); bs[q4*4+1]=f2tf(bv.y);
            bs[q4*4+2]=f2tf(bv.z); bs[q4*4+3]=f2tf(bv.w);
        }
    }
    __syncthreads();

    float c[4][8][4];
#pragma unroll
    for (int i=0;i<4;i++)
#pragma unroll
        for (int j=0;j<8;j++)
#pragma unroll
            for (int h=0;h<4;h++) c[i][j][h]=0.f;

    const int NIT = KD / 16;
    for (int it = 0; it < NIT; it++) {
        int buf = it & 1;
        const float* Asm = AsmB + buf*2560;
        const float* Bsm = BsmB + buf*4224;
        float4 pa0, pa1, pb[4];
        if (it + 1 < NIT) {
            int k0 = (it + 1) * 16;
            const float* ap = A + (size_t)(row0 + arow) * LDA + k0 + akq;
            pa0 = *(const float4*)ap;
            pa1 = *(const float4*)(ap + 4);
            const float* bp = B + (size_t)(k0 + bkr) * LDB + col0 + bnc;
#pragma unroll
            for (int q4 = 0; q4 < 4; q4++) pb[q4] = *(const float4*)(bp + q4*4);
        }
#pragma unroll
        for (int ks = 0; ks < 16; ks += 8) {
            uint32_t af[4][4], bf[8][2];
#pragma unroll
            for (int i = 0; i < 4; i++) {
                int r0i = (wm*64 + i*16 + g) * 20 + ks + t4;
                int r1i = r0i + 8*20;
                af[i][0] = __float_as_uint(Asm[r0i]);
                af[i][1] = __float_as_uint(Asm[r1i]);
                af[i][2] = __float_as_uint(Asm[r0i + 4]);
                af[i][3] = __float_as_uint(Asm[r1i + 4]);
            }
#pragma unroll
            for (int j = 0; j < 8; j++) {
                int nc2 = wn*64 + j*8 + g;
                bf[j][0] = __float_as_uint(Bsm[(ks + t4)*264 + nc2]);
                bf[j][1] = __float_as_uint(Bsm[(ks + t4 + 4)*264 + nc2]);
            }
#pragma unroll
            for (int i = 0; i < 4; i++)
#pragma unroll
                for (int j = 0; j < 8; j++) {
                    asm volatile(
                        "mma.sync.aligned.m16n8k8.row.col.f32.tf32.tf32.f32 "
                        "{%0,%1,%2,%3}, {%4,%5,%6,%7}, {%8,%9}, {%0,%1,%2,%3};\n"
                        : "+f"(c[i][j][0]), "+f"(c[i][j][1]),
                          "+f"(c[i][j][2]), "+f"(c[i][j][3])
                        : "r"(af[i][0]), "r"(af[i][1]), "r"(af[i][2]), "r"(af[i][3]),
                          "r"(bf[j][0]), "r"(bf[j][1]));
                }
        }
        if (it + 1 < NIT) {
            float* as = AsmB + (buf^1)*2560 + arow*20 + akq;
            as[0]=f2tf(pa0.x); as[1]=f2tf(pa0.y); as[2]=f2tf(pa0.z); as[3]=f2tf(pa0.w);
            as[4]=f2tf(pa1.x); as[5]=f2tf(pa1.y); as[6]=f2tf(pa1.z); as[7]=f2tf(pa1.w);
            float* bs = BsmB + (buf^1)*4224 + bkr*264 + bnc;
#pragma unroll
            for (int q4 = 0; q4 < 4; q4++) {
                bs[q4*4+0]=f2tf(pb[q4].x); bs[q4*4+1]=f2tf(pb[q4].y);
                bs[q4*4+2]=f2tf(pb[q4].z); bs[q4*4+3]=f2tf(pb[q4].w);
            }
        }
        __syncthreads();
    }

#pragma unroll
    for (int i = 0; i < 4; i++) {
#pragma unroll
        for (int j = 0; j < 8; j++) {
#pragma unroll
            for (int h = 0; h < 2; h++) {
                int r = row0 + wm*64 + i*16 + g + h*8;
                int cc = col0 + wn*64 + j*8 + 2*t4;
                float v0 = c[i][j][h*2+0], v1 = c[i][j][h*2+1];
                if (EPI == 0) {
                    int b4 = r >> 12, nn = r & 4095;
                    int which = cc >> 9, cs = cc & 511;
                    int hh = cs >> 6, dh = cs & 63;
                    size_t di = ((size_t)(b4*8+hh)*4096 + nn)*64 + dh;
                    if (which == 0) {
                        *(float2*)&C0[di] = make_float2(v0*0.125f, v1*0.125f);
                    } else if (which == 1) {
                        *(float2*)&C1[di] = make_float2(v0, v1);
                    } else {
                        *(float2*)&C2[di] = make_float2(v0, v1);
                    }
                } else {
                    size_t di = (size_t)r*512 + cc;
                    float2 bias = *(const float2*)&e0[cc];
                    float2 xr = *(const float2*)&e1[di];
                    *(float2*)&C0[di] = make_float2(v0+bias.x+xr.x, v1+bias.y+xr.y);
                }
            }
        }
    }
}

// ---------------------------------------------------------------------------
// TF32 GEMM, pinv variant (unchanged, proven): block 128x128, 8 warps 64x32.
// Batched over blockIdx.z (stride 65536): C0 = cA*A + cAB*(A@B)
// ---------------------------------------------------------------------------
__global__ __launch_bounds__(256, 2) void mma_gemm_pinv(
        const float* __restrict__ A, const float* __restrict__ B,
        float* __restrict__ C0, float cA, float cAB) {
    __shared__ float Asm[2][128*20];
    __shared__ float Bsm[2][16*136];
    int tid = threadIdx.x;
    int lane = tid & 31, wid = tid >> 5;
    int wm = wid & 1, wn = wid >> 1;
    int g = lane >> 2, t4 = lane & 3;
    int row0 = blockIdx.y * 128, col0 = blockIdx.x * 128;
    const float* Ag = A + (size_t)blockIdx.z * 65536;
    const float* Bg = B + (size_t)blockIdx.z * 65536;
    int arow = tid >> 1, akq = (tid & 1) * 8;
    int bkr = tid >> 4, bnc = (tid & 15) * 8;

    {
        const float* ap = Ag + (size_t)(row0 + arow) * 256 + akq;
        float4 a0 = *(const float4*)ap;
        float4 a1 = *(const float4*)(ap + 4);
        float* as = &Asm[0][arow*20 + akq];
        as[0]=f2tf(a0.x); as[1]=f2tf(a0.y); as[2]=f2tf(a0.z); as[3]=f2tf(a0.w);
        as[4]=f2tf(a1.x); as[5]=f2tf(a1.y); as[6]=f2tf(a1.z); as[7]=f2tf(a1.w);
        const float* bp = Bg + (size_t)bkr * 256 + col0 + bnc;
        float4 b0 = *(const float4*)bp;
        float4 b1 = *(const float4*)(bp + 4);
        float* bs = &Bsm[0][bkr*136 + bnc];
        bs[0]=f2tf(b0.x); bs[1]=f2tf(b0.y); bs[2]=f2tf(b0.z); bs[3]=f2tf(b0.w);
        bs[4]=f2tf(b1.x); bs[5]=f2tf(b1.y); bs[6]=f2tf(b1.z); bs[7]=f2tf(b1.w);
    }
    __syncthreads();

    float c[4][4][4];
#pragma unroll
    for (int i=0;i<4;i++)
#pragma unroll
        for (int j=0;j<4;j++)
#pragma unroll
            for (int h=0;h<4;h++) c[i][j][h]=0.f;

    const int NIT = 16;
    for (int it = 0; it < NIT; it++) {
        int buf = it & 1;
        float4 pa0, pa1, pb0, pb1;
        if (it + 1 < NIT) {
            int k0 = (it + 1) * 16;
            const float* ap = Ag + (size_t)(row0 + arow) * 256 + k0 + akq;
            pa0 = *(const float4*)ap;
            pa1 = *(const float4*)(ap + 4);
            const float* bp = Bg + (size_t)(k0 + bkr) * 256 + col0 + bnc;
            pb0 = *(const float4*)bp;
            pb1 = *(const float4*)(bp + 4);
        }
#pragma unroll
        for (int ks = 0; ks < 16; ks += 8) {
            uint32_t af[4][4], bf[4][2];
#pragma unroll
            for (int i = 0; i < 4; i++) {
                int r0i = (wm*64 + i*16 + g) * 20 + ks + t4;
                int r1i = r0i + 8*20;
                af[i][0] = __float_as_uint(Asm[buf][r0i]);
                af[i][1] = __float_as_uint(Asm[buf][r1i]);
                af[i][2] = __float_as_uint(Asm[buf][r0i + 4]);
                af[i][3] = __float_as_uint(Asm[buf][r1i + 4]);
            }
#pragma unroll
            for (int j = 0; j < 4; j++) {
                int nc2 = wn*32 + j*8 + g;
                bf[j][0] = __float_as_uint(Bsm[buf][(ks + t4)*136 + nc2]);
                bf[j][1] = __float_as_uint(Bsm[buf][(ks + t4 + 4)*136 + nc2]);
            }
#pragma unroll
            for (int i = 0; i < 4; i++)
#pragma unroll
                for (int j = 0; j < 4; j++) {
                    asm volatile(
                        "mma.sync.aligned.m16n8k8.row.col.f32.tf32.tf32.f32 "
                        "{%0,%1,%2,%3}, {%4,%5,%6,%7}, {%8,%9}, {%0,%1,%2,%3};\n"
                        : "+f"(c[i][j][0]), "+f"(c[i][j][1]),
                          "+f"(c[i][j][2]), "+f"(c[i][j][3])
                        : "r"(af[i][0]), "r"(af[i][1]), "r"(af[i][2]), "r"(af[i][3]),
                          "r"(bf[j][0]), "r"(bf[j][1]));
                }
        }
        if (it + 1 < NIT) {
            int nb = buf ^ 1;
            float* as = &Asm[nb][arow*20 + akq];
            as[0]=f2tf(pa0.x); as[1]=f2tf(pa0.y); as[2]=f2tf(pa0.z); as[3]=f2tf(pa0.w);
            as[4]=f2tf(pa1.x); as[5]=f2tf(pa1.y); as[6]=f2tf(pa1.z); as[7]=f2tf(pa1.w);
            float* bs = &Bsm[nb][bkr*136 + bnc];
            bs[0]=f2tf(pb0.x); bs[1]=f2tf(pb0.y); bs[2]=f2tf(pb0.z); bs[3]=f2tf(pb0.w);
            bs[4]=f2tf(pb1.x); bs[5]=f2tf(pb1.y); bs[6]=f2tf(pb1.z); bs[7]=f2tf(pb1.w);
        }
        __syncthreads();
    }

#pragma unroll
    for (int i = 0; i < 4; i++) {
#pragma unroll
        for (int j = 0; j < 4; j++) {
#pragma unroll
            for (int h = 0; h < 2; h++) {
                int r = row0 + wm*64 + i*16 + g + h*8;
                int cc = col0 + wn*32 + j*8 + 2*t4;
                float v0 = c[i][j][h*2+0], v1 = c[i][j][h*2+1];
                float2 ae = *(const float2*)&Ag[(size_t)r*256 + cc];
                size_t di = (size_t)blockIdx.z*65536 + (size_t)r*256 + cc;
                *(float2*)&C0[di] = make_float2(cA*ae.x + cAB*v0,
                                                cA*ae.y + cAB*v1);
            }
        }
    }
}

// ---------------------------------------------------------------------------
// Landmarks (merged q+k): idx < 524288 -> q, else k
// ---------------------------------------------------------------------------
__global__ void landmark2_kernel(const float* __restrict__ q, const float* __restrict__ k,
                                 float* __restrict__ ql, float* __restrict__ kl) {
    int gidx = blockIdx.x * 256 + threadIdx.x;   // < 1048576
    const float* src = (gidx < 524288) ? q : k;
    float* dst = (gidx < 524288) ? ql : kl;
    int idx = gidx & 524287;
    int dh = idx & 63;
    int mi = (idx >> 6) & 255;
    int bh = idx >> 14;
    const float* p = src + ((size_t)bh*4096 + mi*16)*64 + dh;
    float s = 0.f;
#pragma unroll
    for (int j = 0; j < 16; j++) s += p[j*64];
    dst[idx] = s * 0.0625f;
}

// ---------------------------------------------------------------------------
// a2 = softmax(q_l @ k_l^T)
// ---------------------------------------------------------------------------
__global__ __launch_bounds__(256) void a2_kernel(const float* __restrict__ ql,
        const float* __restrict__ kl, float* __restrict__ a2) {
    __shared__ float klt[256][17];
    int bh = blockIdx.y;
    int r = blockIdx.x * 8 + (threadIdx.x >> 5);
    int lane = threadIdx.x & 31;
    const float* qr = ql + ((size_t)bh*256 + r) * 64;
    const float* kb = kl + (size_t)bh*256*64;
    float acc[8];
#pragma unroll
    for (int i=0;i<8;i++) acc[i]=0.f;
    for (int k0 = 0; k0 < 64; k0 += 16) {
        int c = threadIdx.x;
#pragma unroll
        for (int ii=0; ii<4; ii++) {
            float4 kv = *(const float4*)&kb[(size_t)c*64 + k0 + ii*4];
            klt[c][ii*4+0]=kv.x; klt[c][ii*4+1]=kv.y; klt[c][ii*4+2]=kv.z; klt[c][ii*4+3]=kv.w;
        }
        __syncthreads();
#pragma unroll
        for (int kk=0;kk<16;kk++) {
            float qv = qr[k0+kk];
#pragma unroll
            for (int ii=0;ii<8;ii++) acc[ii] += qv * klt[ii*32+lane][kk];
        }
        __syncthreads();
    }
    float m = acc[0];
#pragma unroll
    for (int ii=1;ii<8;ii++) m = fmaxf(m, acc[ii]);
#pragma unroll
    for (int o=16;o;o>>=1) m = fmaxf(m, __shfl_xor_sync(0xffffffffu,m,o));
    float ssum = 0.f;
#pragma unroll
    for (int ii=0;ii<8;ii++){ acc[ii]=__expf(acc[ii]-m); ssum+=acc[ii]; }
#pragma unroll
    for (int o=16;o;o>>=1) ssum += __shfl_xor_sync(0xffffffffu,ssum,o);
    float inv = 1.f/ssum;
    float* orow = a2 + ((size_t)bh*256 + r) * 256;
#pragma unroll
    for (int ii=0;ii<8;ii++) orow[ii*32+lane] = acc[ii]*inv;
}

// ---------------------------------------------------------------------------
// pinv scalar reductions. a2 is a softmax -> every row-sum == 1 exactly,
// so reference's `col` scalar == 1; only the max column-sum is needed.
// ---------------------------------------------------------------------------
__global__ void red_init_kernel(float* g) { if (threadIdx.x < 2) g[threadIdx.x] = 0.f; }

__global__ void colsum_kernel(const float* __restrict__ a2, float* __restrict__ gred) {
    int bh = blockIdx.x; int j = threadIdx.x;
    const float* base = a2 + (size_t)bh*65536;
    float s = 0.f;
    for (int i=0;i<256;i++) s += fabsf(base[(size_t)i*256 + j]);
#pragma unroll
    for (int o=16;o;o>>=1) s = fmaxf(s, __shfl_xor_sync(0xffffffffu,s,o));
    __shared__ float red[8];
    if ((j&31)==0) red[j>>5]=s;
    __syncthreads();
    if (j==0) {
        float m = red[0];
#pragma unroll
        for (int u=1;u<8;u++) m = fmaxf(m, red[u]);
        atomicMax((int*)&gred[1], __float_as_int(m));
    }
}

__global__ void zinit_kernel(const float* __restrict__ a2, const float* __restrict__ gred,
                             float* __restrict__ z) {
    int idx = blockIdx.x*256 + threadIdx.x;
    int j = idx & 255, i = (idx>>8) & 255, bh = idx >> 16;
    float inv = 1.f/gred[1];           // row-sum max is exactly 1 (softmax rows)
    z[idx] = a2[((size_t)bh*256 + j)*256 + i] * inv;
}

// ---------------------------------------------------------------------------
// fp32 batched GEMM (tiny w2 = pinv @ w, ncols=64)
// ---------------------------------------------------------------------------
__global__ __launch_bounds__(256) void gemm_b_kernel(
        const float* __restrict__ A, const float* __restrict__ B,
        float* __restrict__ C, float cA, float cAB, int ncols) {
    int bh = blockIdx.z;
    int row0 = blockIdx.y * 128;
    int col0 = blockIdx.x * 64;
    const float* Ab = A + (size_t)bh * 65536;
    const float* Bb = B + (size_t)bh * 256 * ncols;
    float* Cb = C + (size_t)bh * 256 * ncols;
    __shared__ float As[16][132];
    __shared__ float Bs[16][64];
    int t = threadIdx.x;
    int tx = t & 15, ty = t >> 4;
    float acc[8][4];
#pragma unroll
    for (int i=0;i<8;i++)
#pragma unroll
        for (int j=0;j<4;j++) acc[i][j]=0.f;
    int alr = t >> 1;
    int alk = (t & 1) * 8;
    int blr = t >> 4;
    int blc = (t & 15) * 4;
    for (int k0 = 0; k0 < 256; k0 += 16) {
#pragma unroll
        for (int ii=0; ii<2; ii++) {
            float4 av = *(const float4*)&Ab[(size_t)(row0+alr)*256 + k0 + alk + ii*4];
            As[alk+ii*4+0][alr]=av.x; As[alk+ii*4+1][alr]=av.y;
            As[alk+ii*4+2][alr]=av.z; As[alk+ii*4+3][alr]=av.w;
        }
        *(float4*)&Bs[blr][blc] = *(const float4*)&Bb[(size_t)(k0+blr)*ncols + col0 + blc];
        __syncthreads();
#pragma unroll
        for (int k=0;k<16;k++) {
            float a[8], b[4];
            *(float4*)&a[0] = *(const float4*)&As[k][ty*8];
            *(float4*)&a[4] = *(const float4*)&As[k][ty*8+4];
            *(float4*)&b[0] = *(const float4*)&Bs[k][tx*4];
#pragma unroll
            for (int i=0;i<8;i++)
#pragma unroll
                for (int j=0;j<4;j++) acc[i][j] += a[i]*b[j];
        }
        __syncthreads();
    }
#pragma unroll
    for (int i=0;i<8;i++) {
        int r = row0 + ty*8 + i;
#pragma unroll
        for (int j=0;j<4;j++) {
            int c = col0 + tx*4 + j;
            float val = cAB * acc[i][j];
            if (cA != 0.f) val += cA * Ab[(size_t)r*256 + c];
            Cb[(size_t)r*ncols + c] = val;
        }
    }
}

// ---------------------------------------------------------------------------
// TF32 tensor-core flash attention (unchanged from R4)
// ---------------------------------------------------------------------------
#define QP 68
#define VP 72
#define OFF_KS   4352
#define OFF_PS   8704
#define OFF_VS   13056
#define OFF_ROWM 17664
#define OFF_ROWL 17728
#define OFF_REDM 17792
#define OFF_REDS 18048
#define SMEM_FLASH_TC ((18304)*4)

__global__ __launch_bounds__(256) void flash_tc_kernel(
        const float* __restrict__ Q, const float* __restrict__ K,
        const float* __restrict__ V, float* __restrict__ O, int nq, int nk) {
    extern __shared__ float sm[];
    float (*Qs)[QP] = (float(*)[QP])sm;
    float (*Ks)[QP] = (float(*)[QP])(sm + OFF_KS);
    float (*Ps)[QP] = (float(*)[QP])(sm + OFF_PS);
    float (*Vs)[VP] = (float(*)[VP])(sm + OFF_VS);
    float* rowm = sm + OFF_ROWM;
    float* rowl = sm + OFF_ROWL;
    float (*redm)[4] = (float(*)[4])(sm + OFF_REDM);
    float (*reds)[4] = (float(*)[4])(sm + OFF_REDS);

    int tid = threadIdx.x;
    int lane = tid & 31, wid = tid >> 5;
    int wm = wid & 1, wn = wid >> 1;
    int g = lane >> 2, t4 = lane & 3;
    int bh = blockIdx.y;
    int q0 = blockIdx.x * 64;
    const float* Qb = Q + ((size_t)bh*nq + q0) * 64;
    const float* Kb = K + (size_t)bh*nk*64;
    const float* Vb = V + (size_t)bh*nk*64;
    float* Ob = O + ((size_t)bh*nq + q0) * 64;

    {
        int r = tid >> 2, kc = (tid & 3) * 16;
#pragma unroll
        for (int ii = 0; ii < 4; ii++) {
            float4 qv = *(const float4*)&Qb[(size_t)r*64 + kc + ii*4];
            Qs[r][kc+ii*4+0]=f2tf(qv.x); Qs[r][kc+ii*4+1]=f2tf(qv.y);
            Qs[r][kc+ii*4+2]=f2tf(qv.z); Qs[r][kc+ii*4+3]=f2tf(qv.w);
        }
    }
    if (tid < 64) { rowm[tid] = -1e30f; rowl[tid] = 0.f; }
    float o[2][2][4];
#pragma unroll
    for (int i=0;i<2;i++)
#pragma unroll
        for (int j=0;j<2;j++)
#pragma unroll
            for (int h=0;h<4;h++) o[i][j][h]=0.f;
    __syncthreads();

    for (int c0 = 0; c0 < nk; c0 += 64) {
        {
            int r = tid >> 2, kc = (tid & 3) * 16;
#pragma unroll
            for (int ii = 0; ii < 4; ii++) {
                float4 kv = *(const float4*)&Kb[(size_t)(c0+r)*64 + kc + ii*4];
                Ks[r][kc+ii*4+0]=f2tf(kv.x); Ks[r][kc+ii*4+1]=f2tf(kv.y);
                Ks[r][kc+ii*4+2]=f2tf(kv.z); Ks[r][kc+ii*4+3]=f2tf(kv.w);
                float4 vv = *(const float4*)&Vb[(size_t)(c0+r)*64 + kc + ii*4];
                Vs[r][kc+ii*4+0]=f2tf(vv.x); Vs[r][kc+ii*4+1]=f2tf(vv.y);
                Vs[r][kc+ii*4+2]=f2tf(vv.z); Vs[r][kc+ii*4+3]=f2tf(vv.w);
            }
        }
        __syncthreads();

        float s[2][2][4];
#pragma unroll
        for (int i=0;i<2;i++)
#pragma unroll
            for (int j=0;j<2;j++)
#pragma unroll
                for (int h=0;h<4;h++) s[i][j][h]=0.f;
#pragma unroll
        for (int ks = 0; ks < 64; ks += 8) {
            uint32_t af[2][4], bf[2][2];
#pragma unroll
            for (int i = 0; i < 2; i++) {
                int r = wm*32 + i*16 + g;
                af[i][0] = __float_as_uint(Qs[r][ks+t4]);
                af[i][1] = __float_as_uint(Qs[r+8][ks+t4]);
                af[i][2] = __float_as_uint(Qs[r][ks+t4+4]);
                af[i][3] = __float_as_uint(Qs[r+8][ks+t4+4]);
            }
#pragma unroll
            for (int j = 0; j < 2; j++) {
                int cc = wn*16 + j*8 + g;
                bf[j][0] = __float_as_uint(Ks[cc][ks+t4]);
                bf[j][1] = __float_as_uint(Ks[cc][ks+t4+4]);
            }
#pragma unroll
            for (int i = 0; i < 2; i++)
#pragma unroll
                for (int j = 0; j < 2; j++) {
                    asm volatile(
                        "mma.sync.aligned.m16n8k8.row.col.f32.tf32.tf32.f32 "
                        "{%0,%1,%2,%3}, {%4,%5,%6,%7}, {%8,%9}, {%0,%1,%2,%3};\n"
                        : "+f"(s[i][j][0]), "+f"(s[i][j][1]),
                          "+f"(s[i][j][2]), "+f"(s[i][j][3])
                        : "r"(af[i][0]), "r"(af[i][1]), "r"(af[i][2]), "r"(af[i][3]),
                          "r"(bf[j][0]), "r"(bf[j][1]));
                }
        }

        float pm[2][2];
#pragma unroll
        for (int i=0;i<2;i++)
#pragma unroll
            for (int h=0;h<2;h++)
                pm[i][h] = fmaxf(fmaxf(s[i][0][2*h], s[i][0][2*h+1]),
                                 fmaxf(s[i][1][2*h], s[i][1][2*h+1]));
#pragma unroll
        for (int off = 1; off <= 2; off <<= 1) {
#pragma unroll
            for (int i=0;i<2;i++)
#pragma unroll
                for (int h=0;h<2;h++)
                    pm[i][h] = fmaxf(pm[i][h], __shfl_xor_sync(0xffffffffu, pm[i][h], off));
        }
        if (t4 == 0) {
#pragma unroll
            for (int i=0;i<2;i++)
#pragma unroll
                for (int h=0;h<2;h++)
                    redm[wm*32 + i*16 + g + h*8][wn] = pm[i][h];
        }
        __syncthreads();

        float mnew[2][2], scale[2][2];
#pragma unroll
        for (int i=0;i<2;i++)
#pragma unroll
            for (int h=0;h<2;h++) {
                int r = wm*32 + i*16 + g + h*8;
                float m = fmaxf(fmaxf(redm[r][0], redm[r][1]),
                                fmaxf(redm[r][2], redm[r][3]));
                float mo = rowm[r];
                mnew[i][h] = fmaxf(mo, m);
                scale[i][h] = __expf(mo - mnew[i][h]);
            }

        float psum[2][2] = {{0.f,0.f},{0.f,0.f}};
#pragma unroll
        for (int i=0;i<2;i++)
#pragma unroll
            for (int j=0;j<2;j++)
#pragma unroll
                for (int h=0;h<2;h++) {
                    int r = wm*32 + i*16 + g + h*8;
                    float p0 = __expf(s[i][j][2*h]   - mnew[i][h]);
                    float p1 = __expf(s[i][j][2*h+1] - mnew[i][h]);
                    *(float2*)&Ps[r][wn*16 + j*8 + 2*t4] = make_float2(f2tf(p0), f2tf(p1));
                    psum[i][h] += p0 + p1;
                    o[i][j][2*h]   *= scale[i][h];
                    o[i][j][2*h+1] *= scale[i][h];
                }
#pragma unroll
        for (int off = 1; off <= 2; off <<= 1) {
#pragma unroll
            for (int i=0;i<2;i++)
#pragma unroll
                for (int h=0;h<2;h++)
                    psum[i][h] += __shfl_xor_sync(0xffffffffu, psum[i][h], off);
        }
        if (t4 == 0) {
#pragma unroll
            for (int i=0;i<2;i++)
#pragma unroll
                for (int h=0;h<2;h++)
                    reds[wm*32 + i*16 + g + h*8][wn] = psum[i][h];
        }
        __syncthreads();

        if (wn == 0 && t4 == 0) {
#pragma unroll
            for (int i=0;i<2;i++)
#pragma unroll
                for (int h=0;h<2;h++) {
                    int r = wm*32 + i*16 + g + h*8;
                    float ps = reds[r][0] + reds[r][1] + reds[r][2] + reds[r][3];
                    rowl[r] = rowl[r]*scale[i][h] + ps;
                    rowm[r] = mnew[i][h];
                }
        }

#pragma unroll
        for (int ks = 0; ks < 64; ks += 8) {
            uint32_t af[2][4], bf[2][2];
#pragma unroll
            for (int i = 0; i < 2; i++) {
                int r = wm*32 + i*16 + g;
                af[i][0] = __float_as_uint(Ps[r][ks+t4]);
                af[i][1] = __float_as_uint(Ps[r+8][ks+t4]);
                af[i][2] = __float_as_uint(Ps[r][ks+t4+4]);
                af[i][3] = __float_as_uint(Ps[r+8][ks+t4+4]);
            }
#pragma unroll
            for (int j = 0; j < 2; j++) {
                int cc = wn*16 + j*8 + g;
                bf[j][0] = __float_as_uint(Vs[ks+t4][cc]);
                bf[j][1] = __float_as_uint(Vs[ks+t4+4][cc]);
            }
#pragma unroll
            for (int i = 0; i < 2; i++)
#pragma unroll
                for (int j = 0; j < 2; j++) {
                    asm volatile(
                        "mma.sync.aligned.m16n8k8.row.col.f32.tf32.tf32.f32 "
                        "{%0,%1,%2,%3}, {%4,%5,%6,%7}, {%8,%9}, {%0,%1,%2,%3};\n"
                        : "+f"(o[i][j][0]), "+f"(o[i][j][1]),
                          "+f"(o[i][j][2]), "+f"(o[i][j][3])
                        : "r"(af[i][0]), "r"(af[i][1]), "r"(af[i][2]), "r"(af[i][3]),
                          "r"(bf[j][0]), "r"(bf[j][1]));
                }
        }
        __syncthreads();
    }

#pragma unroll
    for (int i=0;i<2;i++)
#pragma unroll
        for (int j=0;j<2;j++)
#pragma unroll
            for (int h=0;h<2;h++) {
                int r = wm*32 + i*16 + g + h*8;
                int cc = wn*16 + j*8 + 2*t4;
                float inv = 1.f / rowl[r];
                *(float2*)&Ob[(size_t)r*64 + cc] =
                    make_float2(o[i][j][2*h]*inv, o[i][j][2*h+1]*inv);
            }
}

// ---------------------------------------------------------------------------
// Depthwise seq-conv residual + layout transform
// ---------------------------------------------------------------------------
__global__ __launch_bounds__(256) void conv_kernel(
        const float* __restrict__ attn, const float* __restrict__ v,
        const float* __restrict__ cw, float* __restrict__ attn2) {
    __shared__ float vt[96][64];
    __shared__ float wk[33];
    int bh = blockIdx.y; int h = bh & 7; int b4 = bh >> 3;
    int row0 = blockIdx.x * 64;
    int t = threadIdx.x;
    if (t < 33) wk[t] = cw[h*33 + t];
    const float* vb = v + (size_t)bh*4096*64;
#pragma unroll
    for (int i=0;i<6;i++){
        int f = t + i*256;
        int r = f >> 4;
        int c4 = (f & 15) * 4;
        int gr = row0 - 16 + r;
        float4 val = make_float4(0.f,0.f,0.f,0.f);
        if (gr >= 0 && gr < 4096) val = *(const float4*)&vb[(size_t)gr*64 + c4];
        *(float4*)&vt[r][c4] = val;
    }
    __syncthreads();
    int dh = t & 63;
    int rr = t >> 6;
#pragma unroll
    for (int q=0;q<16;q++){
        int lr = rr + q*4;
        float acc = attn[((size_t)bh*4096 + row0 + lr)*64 + dh];
#pragma unroll
        for (int s=0;s<33;s++) acc += wk[s]*vt[lr+s][dh];
        attn2[((size_t)b4*4096 + row0 + lr)*512 + h*64 + dh] = acc;
    }
}

// ---------------------------------------------------------------------------
// Host orchestration
// ---------------------------------------------------------------------------
#define SMEM_BIG 54272

extern "C" void kernel_launch(void* const* d_in, const int* in_sizes, int n_in,
                              void* d_out, int out_size) {
    const float* x      = (const float*)d_in[0];
    const float* norm_w = (const float*)d_in[1];
    const float* norm_b = (const float*)d_in[2];
    const float* Wqkv   = (const float*)d_in[3];
    const float* Wout   = (const float*)d_in[4];
    const float* bout   = (const float*)d_in[5];
    const float* conv_w = (const float*)d_in[6];
    float* out = (float*)d_out;

    float *xn,*q,*k,*v,*ql,*kl,*a2,*z0,*z1,*t1,*t2,*t3,*w,*w2,*attn,*attn2,*red;
    cudaGetSymbolAddress((void**)&xn,   g_xn);
    cudaGetSymbolAddress((void**)&q,    g_q);
    cudaGetSymbolAddress((void**)&k,    g_k);
    cudaGetSymbolAddress((void**)&v,    g_v);
    cudaGetSymbolAddress((void**)&ql,   g_ql);
    cudaGetSymbolAddress((void**)&kl,   g_kl);
    cudaGetSymbolAddress((void**)&a2,   g_a2);
    cudaGetSymbolAddress((void**)&z0,   g_z0);
    cudaGetSymbolAddress((void**)&z1,   g_z1);
    cudaGetSymbolAddress((void**)&t1,   g_t1);
    cudaGetSymbolAddress((void**)&t2,   g_t2);
    cudaGetSymbolAddress((void**)&t3,   g_t3);
    cudaGetSymbolAddress((void**)&w,    g_w);
    cudaGetSymbolAddress((void**)&w2,   g_w2);
    cudaGetSymbolAddress((void**)&attn, g_attn);
    cudaGetSymbolAddress((void**)&attn2,g_attn2);
    cudaGetSymbolAddress((void**)&red,  g_red);

    cudaFuncSetAttribute(flash_tc_kernel, cudaFuncAttributeMaxDynamicSharedMemorySize, SMEM_FLASH_TC);
    cudaFuncSetAttribute(mma_gemm_big<0,512,1536,512>, cudaFuncAttributeMaxDynamicSharedMemorySize, SMEM_BIG);
    cudaFuncSetAttribute(mma_gemm_big<1,512,512,512>, cudaFuncAttributeMaxDynamicSharedMemorySize, SMEM_BIG);

    // 1. LayerNorm
    ln_kernel<<<16384, 128>>>(x, norm_w, norm_b, xn);
    // 2. QKV projection (big-tile tf32, fused scatter + q scale)
    mma_gemm_big<0,512,1536,512><<<dim3(6,128), 256, SMEM_BIG>>>(
        xn, Wqkv, q, k, v, nullptr, nullptr);
    // 3. landmarks (merged)
    landmark2_kernel<<<4096, 256>>>(q, k, ql, kl);
    // 4. a2 = softmax(q_l k_l^T)
    a2_kernel<<<dim3(32,32), 256>>>(ql, kl, a2);
    // 5. pinv init: row-sum max == 1 exactly; only column-sum max needed
    red_init_kernel<<<1, 32>>>(red);
    colsum_kernel<<<32, 256>>>(a2, red);
    zinit_kernel<<<8192, 256>>>(a2, red, z0);
    // 6. w = softmax(q_l k^T) @ v (tf32 flash)
    flash_tc_kernel<<<dim3(4,32), 256, SMEM_FLASH_TC>>>(ql, k, v, w, 256, 4096);
    // 7. Newton-Schulz pinv (tf32, fused epilogues)
    float* zin = z0; float* zout = z1;
    for (int it = 0; it < 6; it++) {
        mma_gemm_pinv<<<dim3(2,2,32), 256>>>(a2, zin, t1, 0.f,   1.f);
        mma_gemm_pinv<<<dim3(2,2,32), 256>>>(t1, t1, t2, 7.f,   -1.f);
        mma_gemm_pinv<<<dim3(2,2,32), 256>>>(t1, t2, t3, 15.f,  -1.f);
        mma_gemm_pinv<<<dim3(2,2,32), 256>>>(zin, t3, zout, 3.25f, -0.25f);
        float* tmp = zin; zin = zout; zout = tmp;
    }
    // 8. w2 = pinv(a2) @ w (small, fp32)
    gemm_b_kernel<<<dim3(1,2,32), 256>>>(zin, w, w2, 0.f, 1.f, 64);
    // 9. attn = softmax(q k_l^T) @ w2 (tf32 flash)
    flash_tc_kernel<<<dim3(64,32), 256, SMEM_FLASH_TC>>>(q, kl, w2, attn, 4096, 256);
    // 10. conv residual + layout
    conv_kernel<<<dim3(64,32), 256>>>(attn, v, conv_w, attn2);
    // 11. output projection + bias + input residual (big-tile tf32)
    mma_gemm_big<1,512,512,512><<<dim3(2,128), 256, SMEM_BIG>>>(
        attn2, Wout, out, nullptr, nullptr, bout, x);
}

// round 6
// speedup vs baseline: 1.0987x; 1.0987x over previous
#include <cuda_runtime.h>
#include <cuda_bf16.h>
#include <cstdint>

// ---------------------------------------------------------------------------
// Problem constants: b=4, n=4096, D=512, H=8, dh=64, M=256, l=16, 6 iters,
// conv k=33, eps=1e-5
// ---------------------------------------------------------------------------
#define NB   (4*4096*512)
#define MM   (32*256*256)
#define MD   (32*256*64)

__device__ float g_xn[NB];
__device__ float g_q[NB];
__device__ float g_k[NB];
__device__ float g_v[NB];
__device__ float g_ql[MD];
__device__ float g_kl[MD];
__device__ float g_a2[MM];
__device__ float g_z0[MM];
__device__ float g_z1[MM];
__device__ float g_t1[MM];   // also flash1 split-K O partials (4*32*256*64 = MM)
__device__ float g_t2[MM];   // also flash1 split-K m/l partials
__device__ float g_t3[MM];
__device__ float g_w[MD];
__device__ float g_w2[MD];
__device__ float g_attn[NB];
__device__ float g_attn2[NB];
__device__ float g_red[2];

__device__ __forceinline__ float f2tf(float x) {
    uint32_t u;
    asm("cvt.rna.tf32.f32 %0, %1;" : "=r"(u) : "f"(x));
    return __uint_as_float(u);
}

// ---------------------------------------------------------------------------
// LayerNorm
// ---------------------------------------------------------------------------
__global__ void ln_kernel(const float* __restrict__ x, const float* __restrict__ w,
                          const float* __restrict__ bb, float* __restrict__ out) {
    int row = blockIdx.x;
    const float* xr = x + (size_t)row * 512;
    float* orow = out + (size_t)row * 512;
    int t = threadIdx.x;
    float v[4];
    float s = 0.f;
#pragma unroll
    for (int i = 0; i < 4; i++) { v[i] = xr[t + 128*i]; s += v[i]; }
#pragma unroll
    for (int o = 16; o; o >>= 1) s += __shfl_xor_sync(0xffffffffu, s, o);
    __shared__ float red[4];
    if ((t & 31) == 0) red[t >> 5] = s;
    __syncthreads();
    float mean = (red[0]+red[1]+red[2]+red[3]) * (1.f/512.f);
    float vs = 0.f;
#pragma unroll
    for (int i = 0; i < 4; i++) { float d = v[i]-mean; vs += d*d; }
#pragma unroll
    for (int o = 16; o; o >>= 1) vs += __shfl_xor_sync(0xffffffffu, vs, o);
    __syncthreads();
    if ((t & 31) == 0) red[t >> 5] = vs;
    __syncthreads();
    float var = (red[0]+red[1]+red[2]+red[3]) * (1.f/512.f);
    float rstd = rsqrtf(var + 1e-5f);
#pragma unroll
    for (int i = 0; i < 4; i++) {
        int c = t + 128*i;
        orow[c] = (v[i]-mean)*rstd*w[c] + bb[c];
    }
}

// ---------------------------------------------------------------------------
// TF32 GEMM (R4 proven config): block 128x128, BK=16, 8 warps 64x32, occ 2.
// EPI 0: QKV scatter. EPI 1: bias + residual.
// ---------------------------------------------------------------------------
template<int EPI, int LDA, int LDB, int KD>
__global__ __launch_bounds__(256, 2) void mma_gemm(
        const float* __restrict__ A, const float* __restrict__ B,
        float* __restrict__ C0, float* __restrict__ C1, float* __restrict__ C2,
        const float* __restrict__ e0, const float* __restrict__ e1) {
    __shared__ float Asm[2][128*20];
    __shared__ float Bsm[2][16*136];
    int tid = threadIdx.x;
    int lane = tid & 31, wid = tid >> 5;
    int wm = wid & 1, wn = wid >> 1;
    int g = lane >> 2, t4 = lane & 3;
    int row0 = blockIdx.y * 128, col0 = blockIdx.x * 128;
    int arow = tid >> 1, akq = (tid & 1) * 8;
    int bkr = tid >> 4, bnc = (tid & 15) * 8;

    {
        const float* ap = A + (size_t)(row0 + arow) * LDA + akq;
        float4 a0 = *(const float4*)ap;
        float4 a1 = *(const float4*)(ap + 4);
        float* as = &Asm[0][arow*20 + akq];
        as[0]=f2tf(a0.x); as[1]=f2tf(a0.y); as[2]=f2tf(a0.z); as[3]=f2tf(a0.w);
        as[4]=f2tf(a1.x); as[5]=f2tf(a1.y); as[6]=f2tf(a1.z); as[7]=f2tf(a1.w);
        const float* bp = B + (size_t)bkr * LDB + col0 + bnc;
        float4 b0 = *(const float4*)bp;
        float4 b1 = *(const float4*)(bp + 4);
        float* bs = &Bsm[0][bkr*136 + bnc];
        bs[0]=f2tf(b0.x); bs[1]=f2tf(b0.y); bs[2]=f2tf(b0.z); bs[3]=f2tf(b0.w);
        bs[4]=f2tf(b1.x); bs[5]=f2tf(b1.y); bs[6]=f2tf(b1.z); bs[7]=f2tf(b1.w);
    }
    __syncthreads();

    float c[4][4][4];
#pragma unroll
    for (int i=0;i<4;i++)
#pragma unroll
        for (int j=0;j<4;j++)
#pragma unroll
            for (int h=0;h<4;h++) c[i][j][h]=0.f;

    const int NIT = KD / 16;
    for (int it = 0; it < NIT; it++) {
        int buf = it & 1;
        float4 pa0, pa1, pb0, pb1;
        if (it + 1 < NIT) {
            int k0 = (it + 1) * 16;
            const float* ap = A + (size_t)(row0 + arow) * LDA + k0 + akq;
            pa0 = *(const float4*)ap;
            pa1 = *(const float4*)(ap + 4);
            const float* bp = B + (size_t)(k0 + bkr) * LDB + col0 + bnc;
            pb0 = *(const float4*)bp;
            pb1 = *(const float4*)(bp + 4);
        }
#pragma unroll
        for (int ks = 0; ks < 16; ks += 8) {
            uint32_t af[4][4], bf[4][2];
#pragma unroll
            for (int i = 0; i < 4; i++) {
                int r0i = (wm*64 + i*16 + g) * 20 + ks + t4;
                int r1i = r0i + 8*20;
                af[i][0] = __float_as_uint(Asm[buf][r0i]);
                af[i][1] = __float_as_uint(Asm[buf][r1i]);
                af[i][2] = __float_as_uint(Asm[buf][r0i + 4]);
                af[i][3] = __float_as_uint(Asm[buf][r1i + 4]);
            }
#pragma unroll
            for (int j = 0; j < 4; j++) {
                int nc2 = wn*32 + j*8 + g;
                bf[j][0] = __float_as_uint(Bsm[buf][(ks + t4)*136 + nc2]);
                bf[j][1] = __float_as_uint(Bsm[buf][(ks + t4 + 4)*136 + nc2]);
            }
#pragma unroll
            for (int i = 0; i < 4; i++)
#pragma unroll
                for (int j = 0; j < 4; j++) {
                    asm volatile(
                        "mma.sync.aligned.m16n8k8.row.col.f32.tf32.tf32.f32 "
                        "{%0,%1,%2,%3}, {%4,%5,%6,%7}, {%8,%9}, {%0,%1,%2,%3};\n"
                        : "+f"(c[i][j][0]), "+f"(c[i][j][1]),
                          "+f"(c[i][j][2]), "+f"(c[i][j][3])
                        : "r"(af[i][0]), "r"(af[i][1]), "r"(af[i][2]), "r"(af[i][3]),
                          "r"(bf[j][0]), "r"(bf[j][1]));
                }
        }
        if (it + 1 < NIT) {
            int nb = buf ^ 1;
            float* as = &Asm[nb][arow*20 + akq];
            as[0]=f2tf(pa0.x); as[1]=f2tf(pa0.y); as[2]=f2tf(pa0.z); as[3]=f2tf(pa0.w);
            as[4]=f2tf(pa1.x); as[5]=f2tf(pa1.y); as[6]=f2tf(pa1.z); as[7]=f2tf(pa1.w);
            float* bs = &Bsm[nb][bkr*136 + bnc];
            bs[0]=f2tf(pb0.x); bs[1]=f2tf(pb0.y); bs[2]=f2tf(pb0.z); bs[3]=f2tf(pb0.w);
            bs[4]=f2tf(pb1.x); bs[5]=f2tf(pb1.y); bs[6]=f2tf(pb1.z); bs[7]=f2tf(pb1.w);
        }
        __syncthreads();
    }

#pragma unroll
    for (int i = 0; i < 4; i++) {
#pragma unroll
        for (int j = 0; j < 4; j++) {
#pragma unroll
            for (int h = 0; h < 2; h++) {
                int r = row0 + wm*64 + i*16 + g + h*8;
                int cc = col0 + wn*32 + j*8 + 2*t4;
                float v0 = c[i][j][h*2+0], v1 = c[i][j][h*2+1];
                if (EPI == 0) {
                    int b4 = r >> 12, nn = r & 4095;
                    int which = cc >> 9, cs = cc & 511;
                    int hh = cs >> 6, dh = cs & 63;
                    size_t di = ((size_t)(b4*8+hh)*4096 + nn)*64 + dh;
                    if (which == 0) {
                        *(float2*)&C0[di] = make_float2(v0*0.125f, v1*0.125f);
                    } else if (which == 1) {
                        *(float2*)&C1[di] = make_float2(v0, v1);
                    } else {
                        *(float2*)&C2[di] = make_float2(v0, v1);
                    }
                } else {
                    size_t di = (size_t)r*512 + cc;
                    float2 bias = *(const float2*)&e0[cc];
                    float2 xr = *(const float2*)&e1[di];
                    *(float2*)&C0[di] = make_float2(v0+bias.x+xr.x, v1+bias.y+xr.y);
                }
            }
        }
    }
}

// ---------------------------------------------------------------------------
// TF32 GEMM, pinv variant: batched over z (stride 65536): C0 = cA*A + cAB*(A@B)
// ---------------------------------------------------------------------------
__global__ __launch_bounds__(256, 2) void mma_gemm_pinv(
        const float* __restrict__ A, const float* __restrict__ B,
        float* __restrict__ C0, float cA, float cAB) {
    __shared__ float Asm[2][128*20];
    __shared__ float Bsm[2][16*136];
    int tid = threadIdx.x;
    int lane = tid & 31, wid = tid >> 5;
    int wm = wid & 1, wn = wid >> 1;
    int g = lane >> 2, t4 = lane & 3;
    int row0 = blockIdx.y * 128, col0 = blockIdx.x * 128;
    const float* Ag = A + (size_t)blockIdx.z * 65536;
    const float* Bg = B + (size_t)blockIdx.z * 65536;
    int arow = tid >> 1, akq = (tid & 1) * 8;
    int bkr = tid >> 4, bnc = (tid & 15) * 8;

    {
        const float* ap = Ag + (size_t)(row0 + arow) * 256 + akq;
        float4 a0 = *(const float4*)ap;
        float4 a1 = *(const float4*)(ap + 4);
        float* as = &Asm[0][arow*20 + akq];
        as[0]=f2tf(a0.x); as[1]=f2tf(a0.y); as[2]=f2tf(a0.z); as[3]=f2tf(a0.w);
        as[4]=f2tf(a1.x); as[5]=f2tf(a1.y); as[6]=f2tf(a1.z); as[7]=f2tf(a1.w);
        const float* bp = Bg + (size_t)bkr * 256 + col0 + bnc;
        float4 b0 = *(const float4*)bp;
        float4 b1 = *(const float4*)(bp + 4);
        float* bs = &Bsm[0][bkr*136 + bnc];
        bs[0]=f2tf(b0.x); bs[1]=f2tf(b0.y); bs[2]=f2tf(b0.z); bs[3]=f2tf(b0.w);
        bs[4]=f2tf(b1.x); bs[5]=f2tf(b1.y); bs[6]=f2tf(b1.z); bs[7]=f2tf(b1.w);
    }
    __syncthreads();

    float c[4][4][4];
#pragma unroll
    for (int i=0;i<4;i++)
#pragma unroll
        for (int j=0;j<4;j++)
#pragma unroll
            for (int h=0;h<4;h++) c[i][j][h]=0.f;

    const int NIT = 16;
    for (int it = 0; it < NIT; it++) {
        int buf = it & 1;
        float4 pa0, pa1, pb0, pb1;
        if (it + 1 < NIT) {
            int k0 = (it + 1) * 16;
            const float* ap = Ag + (size_t)(row0 + arow) * 256 + k0 + akq;
            pa0 = *(const float4*)ap;
            pa1 = *(const float4*)(ap + 4);
            const float* bp = Bg + (size_t)(k0 + bkr) * 256 + col0 + bnc;
            pb0 = *(const float4*)bp;
            pb1 = *(const float4*)(bp + 4);
        }
#pragma unroll
        for (int ks = 0; ks < 16; ks += 8) {
            uint32_t af[4][4], bf[4][2];
#pragma unroll
            for (int i = 0; i < 4; i++) {
                int r0i = (wm*64 + i*16 + g) * 20 + ks + t4;
                int r1i = r0i + 8*20;
                af[i][0] = __float_as_uint(Asm[buf][r0i]);
                af[i][1] = __float_as_uint(Asm[buf][r1i]);
                af[i][2] = __float_as_uint(Asm[buf][r0i + 4]);
                af[i][3] = __float_as_uint(Asm[buf][r1i + 4]);
            }
#pragma unroll
            for (int j = 0; j < 4; j++) {
                int nc2 = wn*32 + j*8 + g;
                bf[j][0] = __float_as_uint(Bsm[buf][(ks + t4)*136 + nc2]);
                bf[j][1] = __float_as_uint(Bsm[buf][(ks + t4 + 4)*136 + nc2]);
            }
#pragma unroll
            for (int i = 0; i < 4; i++)
#pragma unroll
                for (int j = 0; j < 4; j++) {
                    asm volatile(
                        "mma.sync.aligned.m16n8k8.row.col.f32.tf32.tf32.f32 "
                        "{%0,%1,%2,%3}, {%4,%5,%6,%7}, {%8,%9}, {%0,%1,%2,%3};\n"
                        : "+f"(c[i][j][0]), "+f"(c[i][j][1]),
                          "+f"(c[i][j][2]), "+f"(c[i][j][3])
                        : "r"(af[i][0]), "r"(af[i][1]), "r"(af[i][2]), "r"(af[i][3]),
                          "r"(bf[j][0]), "r"(bf[j][1]));
                }
        }
        if (it + 1 < NIT) {
            int nb = buf ^ 1;
            float* as = &Asm[nb][arow*20 + akq];
            as[0]=f2tf(pa0.x); as[1]=f2tf(pa0.y); as[2]=f2tf(pa0.z); as[3]=f2tf(pa0.w);
            as[4]=f2tf(pa1.x); as[5]=f2tf(pa1.y); as[6]=f2tf(pa1.z); as[7]=f2tf(pa1.w);
            float* bs = &Bsm[nb][bkr*136 + bnc];
            bs[0]=f2tf(pb0.x); bs[1]=f2tf(pb0.y); bs[2]=f2tf(pb0.z); bs[3]=f2tf(pb0.w);
            bs[4]=f2tf(pb1.x); bs[5]=f2tf(pb1.y); bs[6]=f2tf(pb1.z); bs[7]=f2tf(pb1.w);
        }
        __syncthreads();
    }

#pragma unroll
    for (int i = 0; i < 4; i++) {
#pragma unroll
        for (int j = 0; j < 4; j++) {
#pragma unroll
            for (int h = 0; h < 2; h++) {
                int r = row0 + wm*64 + i*16 + g + h*8;
                int cc = col0 + wn*32 + j*8 + 2*t4;
                float v0 = c[i][j][h*2+0], v1 = c[i][j][h*2+1];
                float2 ae = *(const float2*)&Ag[(size_t)r*256 + cc];
                size_t di = (size_t)blockIdx.z*65536 + (size_t)r*256 + cc;
                *(float2*)&C0[di] = make_float2(cA*ae.x + cAB*v0,
                                                cA*ae.y + cAB*v1);
            }
        }
    }
}

// ---------------------------------------------------------------------------
// TF32 MMA w2 = zin @ w  [32 batches: 256x256 @ 256x64].
// Block 128x64 (8 warps: wm=wid&3 32 rows, wn=wid>>2 32 cols), BK=16.
// ---------------------------------------------------------------------------
__global__ __launch_bounds__(256, 2) void mma_w2_kernel(
        const float* __restrict__ A, const float* __restrict__ B, float* __restrict__ C) {
    __shared__ float Asm[2][128*20];
    __shared__ float Bsm[2][16*72];
    int tid = threadIdx.x;
    int lane = tid & 31, wid = tid >> 5;
    int wm = wid & 3, wn = wid >> 2;
    int g = lane >> 2, t4 = lane & 3;
    int row0 = blockIdx.y * 128;
    const float* Ag = A + (size_t)blockIdx.z * 65536;
    const float* Bg = B + (size_t)blockIdx.z * 16384;
    float* Cg = C + (size_t)blockIdx.z * 16384;
    int arow = tid >> 1, akq = (tid & 1) * 8;
    int bkr = tid >> 4, bnc = (tid & 15) * 4;

    {
        const float* ap = Ag + (size_t)(row0 + arow) * 256 + akq;
        float4 a0 = *(const float4*)ap;
        float4 a1 = *(const float4*)(ap + 4);
        float* as = &Asm[0][arow*20 + akq];
        as[0]=f2tf(a0.x); as[1]=f2tf(a0.y); as[2]=f2tf(a0.z); as[3]=f2tf(a0.w);
        as[4]=f2tf(a1.x); as[5]=f2tf(a1.y); as[6]=f2tf(a1.z); as[7]=f2tf(a1.w);
        float4 bv = *(const float4*)(Bg + (size_t)bkr * 64 + bnc);
        float* bs = &Bsm[0][bkr*72 + bnc];
        bs[0]=f2tf(bv.x); bs[1]=f2tf(bv.y); bs[2]=f2tf(bv.z); bs[3]=f2tf(bv.w);
    }
    __syncthreads();

    float c[2][4][4];
#pragma unroll
    for (int i=0;i<2;i++)
#pragma unroll
        for (int j=0;j<4;j++)
#pragma unroll
            for (int h=0;h<4;h++) c[i][j][h]=0.f;

    const int NIT = 16;
    for (int it = 0; it < NIT; it++) {
        int buf = it & 1;
        float4 pa0, pa1, pb;
        if (it + 1 < NIT) {
            int k0 = (it + 1) * 16;
            const float* ap = Ag + (size_t)(row0 + arow) * 256 + k0 + akq;
            pa0 = *(const float4*)ap;
            pa1 = *(const float4*)(ap + 4);
            pb = *(const float4*)(Bg + (size_t)(k0 + bkr) * 64 + bnc);
        }
#pragma unroll
        for (int ks = 0; ks < 16; ks += 8) {
            uint32_t af[2][4], bf[4][2];
#pragma unroll
            for (int i = 0; i < 2; i++) {
                int r0i = (wm*32 + i*16 + g) * 20 + ks + t4;
                int r1i = r0i + 8*20;
                af[i][0] = __float_as_uint(Asm[buf][r0i]);
                af[i][1] = __float_as_uint(Asm[buf][r1i]);
                af[i][2] = __float_as_uint(Asm[buf][r0i + 4]);
                af[i][3] = __float_as_uint(Asm[buf][r1i + 4]);
            }
#pragma unroll
            for (int j = 0; j < 4; j++) {
                int nc2 = wn*32 + j*8 + g;
                bf[j][0] = __float_as_uint(Bsm[buf][(ks + t4)*72 + nc2]);
                bf[j][1] = __float_as_uint(Bsm[buf][(ks + t4 + 4)*72 + nc2]);
            }
#pragma unroll
            for (int i = 0; i < 2; i++)
#pragma unroll
                for (int j = 0; j < 4; j++) {
                    asm volatile(
                        "mma.sync.aligned.m16n8k8.row.col.f32.tf32.tf32.f32 "
                        "{%0,%1,%2,%3}, {%4,%5,%6,%7}, {%8,%9}, {%0,%1,%2,%3};\n"
                        : "+f"(c[i][j][0]), "+f"(c[i][j][1]),
                          "+f"(c[i][j][2]), "+f"(c[i][j][3])
                        : "r"(af[i][0]), "r"(af[i][1]), "r"(af[i][2]), "r"(af[i][3]),
                          "r"(bf[j][0]), "r"(bf[j][1]));
                }
        }
        if (it + 1 < NIT) {
            int nb = buf ^ 1;
            float* as = &Asm[nb][arow*20 + akq];
            as[0]=f2tf(pa0.x); as[1]=f2tf(pa0.y); as[2]=f2tf(pa0.z); as[3]=f2tf(pa0.w);
            as[4]=f2tf(pa1.x); as[5]=f2tf(pa1.y); as[6]=f2tf(pa1.z); as[7]=f2tf(pa1.w);
            float* bs = &Bsm[nb][bkr*72 + bnc];
            bs[0]=f2tf(pb.x); bs[1]=f2tf(pb.y); bs[2]=f2tf(pb.z); bs[3]=f2tf(pb.w);
        }
        __syncthreads();
    }

#pragma unroll
    for (int i = 0; i < 2; i++)
#pragma unroll
        for (int j = 0; j < 4; j++)
#pragma unroll
            for (int h = 0; h < 2; h++) {
                int r = row0 + wm*32 + i*16 + g + h*8;
                int cc = wn*32 + j*8 + 2*t4;
                *(float2*)&Cg[(size_t)r*64 + cc] =
                    make_float2(c[i][j][h*2+0], c[i][j][h*2+1]);
            }
}

// ---------------------------------------------------------------------------
// TF32 MMA a2 = softmax(q_l @ k_l^T): block = 128 rows x full 256 cols.
// 8 warps: wm=wid&1 (64 rows), wn=wid>>1 (64 cols). Grid (2, 32).
// Dyn smem: Qs 128*68 + Ks 256*68 + redm 512 + reds 512 = 27136 floats.
// ---------------------------------------------------------------------------
#define A2_KS   8704
#define A2_RM   26112
#define A2_RS   26624
#define SMEM_A2 (27136*4)
__global__ __launch_bounds__(256, 1) void a2_tc_kernel(
        const float* __restrict__ ql, const float* __restrict__ kl,
        float* __restrict__ a2) {
    extern __shared__ float sm2[];
    float* Qs = sm2;                       // [128][68]
    float* Ks = sm2 + A2_KS;               // [256][68]
    float (*redm)[4] = (float(*)[4])(sm2 + A2_RM);
    float (*reds)[4] = (float(*)[4])(sm2 + A2_RS);

    int tid = threadIdx.x;
    int lane = tid & 31, wid = tid >> 5;
    int wm = wid & 1, wn = wid >> 1;
    int g = lane >> 2, t4 = lane & 3;
    int bh = blockIdx.y;
    int row0 = blockIdx.x * 128;
    const float* qb = ql + ((size_t)bh*256 + row0) * 64;
    const float* kb = kl + (size_t)bh*256*64;

    // coalesced loads + tf32 round
    for (int i = tid*4; i < 8192; i += 1024) {
        float4 qv = *(const float4*)&qb[i];
        int r = i >> 6, cc = i & 63;
        float* qs = &Qs[r*68 + cc];
        qs[0]=f2tf(qv.x); qs[1]=f2tf(qv.y); qs[2]=f2tf(qv.z); qs[3]=f2tf(qv.w);
    }
    for (int i = tid*4; i < 16384; i += 1024) {
        float4 kv = *(const float4*)&kb[i];
        int r = i >> 6, cc = i & 63;
        float* ks = &Ks[r*68 + cc];
        ks[0]=f2tf(kv.x); ks[1]=f2tf(kv.y); ks[2]=f2tf(kv.z); ks[3]=f2tf(kv.w);
    }
    __syncthreads();

    float c[4][8][4];
#pragma unroll
    for (int i=0;i<4;i++)
#pragma unroll
        for (int j=0;j<8;j++)
#pragma unroll
            for (int h=0;h<4;h++) c[i][j][h]=0.f;

#pragma unroll
    for (int ks = 0; ks < 64; ks += 8) {
        uint32_t af[4][4], bf[8][2];
#pragma unroll
        for (int i = 0; i < 4; i++) {
            int r0i = (wm*64 + i*16 + g)*68 + ks + t4;
            int r1i = r0i + 8*68;
            af[i][0] = __float_as_uint(Qs[r0i]);
            af[i][1] = __float_as_uint(Qs[r1i]);
            af[i][2] = __float_as_uint(Qs[r0i + 4]);
            af[i][3] = __float_as_uint(Qs[r1i + 4]);
        }
#pragma unroll
        for (int j = 0; j < 8; j++) {
            int cr = (wn*64 + j*8 + g)*68 + ks + t4;
            bf[j][0] = __float_as_uint(Ks[cr]);
            bf[j][1] = __float_as_uint(Ks[cr + 4]);
        }
#pragma unroll
        for (int i = 0; i < 4; i++)
#pragma unroll
            for (int j = 0; j < 8; j++) {
                asm volatile(
                    "mma.sync.aligned.m16n8k8.row.col.f32.tf32.tf32.f32 "
                    "{%0,%1,%2,%3}, {%4,%5,%6,%7}, {%8,%9}, {%0,%1,%2,%3};\n"
                    : "+f"(c[i][j][0]), "+f"(c[i][j][1]),
                      "+f"(c[i][j][2]), "+f"(c[i][j][3])
                    : "r"(af[i][0]), "r"(af[i][1]), "r"(af[i][2]), "r"(af[i][3]),
                      "r"(bf[j][0]), "r"(bf[j][1]));
            }
    }

    // row max over warp's 64 cols, quad-reduce, cross-warp via smem
    float pm[4][2];
#pragma unroll
    for (int i=0;i<4;i++)
#pragma unroll
        for (int h=0;h<2;h++) {
            float m = c[i][0][2*h];
#pragma unroll
            for (int j=0;j<8;j++) {
                m = fmaxf(m, c[i][j][2*h]);
                m = fmaxf(m, c[i][j][2*h+1]);
            }
#pragma unroll
            for (int off = 1; off <= 2; off <<= 1)
                m = fmaxf(m, __shfl_xor_sync(0xffffffffu, m, off));
            pm[i][h] = m;
        }
    if (t4 == 0) {
#pragma unroll
        for (int i=0;i<4;i++)
#pragma unroll
            for (int h=0;h<2;h++)
                redm[wm*64 + i*16 + g + h*8][wn] = pm[i][h];
    }
    __syncthreads();

    float psum[4][2];
#pragma unroll
    for (int i=0;i<4;i++)
#pragma unroll
        for (int h=0;h<2;h++) {
            int r = wm*64 + i*16 + g + h*8;
            float m = fmaxf(fmaxf(redm[r][0], redm[r][1]),
                            fmaxf(redm[r][2], redm[r][3]));
            float s = 0.f;
#pragma unroll
            for (int j=0;j<8;j++) {
                float p0 = __expf(c[i][j][2*h]   - m);
                float p1 = __expf(c[i][j][2*h+1] - m);
                c[i][j][2*h] = p0; c[i][j][2*h+1] = p1;
                s += p0 + p1;
            }
#pragma unroll
            for (int off = 1; off <= 2; off <<= 1)
                s += __shfl_xor_sync(0xffffffffu, s, off);
            psum[i][h] = s;
        }
    if (t4 == 0) {
#pragma unroll
        for (int i=0;i<4;i++)
#pragma unroll
            for (int h=0;h<2;h++)
                reds[wm*64 + i*16 + g + h*8][wn] = psum[i][h];
    }
    __syncthreads();

#pragma unroll
    for (int i=0;i<4;i++)
#pragma unroll
        for (int h=0;h<2;h++) {
            int r = wm*64 + i*16 + g + h*8;
            float inv = 1.f / (reds[r][0]+reds[r][1]+reds[r][2]+reds[r][3]);
            float* orow = a2 + ((size_t)bh*256 + row0 + r) * 256;
#pragma unroll
            for (int j=0;j<8;j++) {
                int cc = wn*64 + j*8 + 2*t4;
                *(float2*)&orow[cc] = make_float2(c[i][j][2*h]*inv, c[i][j][2*h+1]*inv);
            }
        }
}

// ---------------------------------------------------------------------------
// Landmarks (merged q+k)
// ---------------------------------------------------------------------------
__global__ void landmark2_kernel(const float* __restrict__ q, const float* __restrict__ k,
                                 float* __restrict__ ql, float* __restrict__ kl) {
    int gidx = blockIdx.x * 256 + threadIdx.x;
    const float* src = (gidx < 524288) ? q : k;
    float* dst = (gidx < 524288) ? ql : kl;
    int idx = gidx & 524287;
    int dh = idx & 63;
    int mi = (idx >> 6) & 255;
    int bh = idx >> 14;
    const float* p = src + ((size_t)bh*4096 + mi*16)*64 + dh;
    float s = 0.f;
#pragma unroll
    for (int j = 0; j < 16; j++) s += p[j*64];
    dst[idx] = s * 0.0625f;
}

// ---------------------------------------------------------------------------
// pinv scalars: row-sum max == 1 exactly (softmax rows); need col-sum max.
// ---------------------------------------------------------------------------
__global__ void red_init_kernel(float* g) { if (threadIdx.x < 2) g[threadIdx.x] = 0.f; }

__global__ void colsum_kernel(const float* __restrict__ a2, float* __restrict__ gred) {
    int bh = blockIdx.x; int j = threadIdx.x;
    const float* base = a2 + (size_t)bh*65536;
    float s = 0.f;
    for (int i=0;i<256;i++) s += fabsf(base[(size_t)i*256 + j]);
#pragma unroll
    for (int o=16;o;o>>=1) s = fmaxf(s, __shfl_xor_sync(0xffffffffu,s,o));
    __shared__ float red[8];
    if ((j&31)==0) red[j>>5]=s;
    __syncthreads();
    if (j==0) {
        float m = red[0];
#pragma unroll
        for (int u=1;u<8;u++) m = fmaxf(m, red[u]);
        atomicMax((int*)&gred[1], __float_as_int(m));
    }
}

__global__ void zinit_kernel(const float* __restrict__ a2, const float* __restrict__ gred,
                             float* __restrict__ z) {
    int idx = blockIdx.x*256 + threadIdx.x;
    int j = idx & 255, i = (idx>>8) & 255, bh = idx >> 16;
    float inv = 1.f/gred[1];
    z[idx] = a2[((size_t)bh*256 + j)*256 + i] * inv;
}

// ---------------------------------------------------------------------------
// TF32 flash attention with optional split-K partial output.
// If lpart != nullptr: O gets UN-divided accumulators at
//   [(blockIdx.z*32+bh)*nq + row], plus per-row m/l into mpart/lpart.
// K/V chunk: rows [blockIdx.z*chunk, +chunk).
// ---------------------------------------------------------------------------
#define QP 68
#define VP 72
#define OFF_KS   4352
#define OFF_PS   8704
#define OFF_VS   13056
#define OFF_ROWM 17664
#define OFF_ROWL 17728
#define OFF_REDM 17792
#define OFF_REDS 18048
#define SMEM_FLASH_TC ((18304)*4)

__global__ __launch_bounds__(256) void flash_tc_kernel(
        const float* __restrict__ Q, const float* __restrict__ K,
        const float* __restrict__ V, float* __restrict__ O, int nq, int nk,
        int chunk, float* __restrict__ mpart, float* __restrict__ lpart) {
    extern __shared__ float sm[];
    float (*Qs)[QP] = (float(*)[QP])sm;
    float (*Ks)[QP] = (float(*)[QP])(sm + OFF_KS);
    float (*Ps)[QP] = (float(*)[QP])(sm + OFF_PS);
    float (*Vs)[VP] = (float(*)[VP])(sm + OFF_VS);
    float* rowm = sm + OFF_ROWM;
    float* rowl = sm + OFF_ROWL;
    float (*redm)[4] = (float(*)[4])(sm + OFF_REDM);
    float (*reds)[4] = (float(*)[4])(sm + OFF_REDS);

    int tid = threadIdx.x;
    int lane = tid & 31, wid = tid >> 5;
    int wm = wid & 1, wn = wid >> 1;
    int g = lane >> 2, t4 = lane & 3;
    int bh = blockIdx.y;
    int q0 = blockIdx.x * 64;
    size_t koff = (size_t)blockIdx.z * chunk * 64;
    const float* Qb = Q + ((size_t)bh*nq + q0) * 64;
    const float* Kb = K + (size_t)bh*nk*64 + koff;
    const float* Vb = V + (size_t)bh*nk*64 + koff;

    {
        int r = tid >> 2, kc = (tid & 3) * 16;
#pragma unroll
        for (int ii = 0; ii < 4; ii++) {
            float4 qv = *(const float4*)&Qb[(size_t)r*64 + kc + ii*4];
            Qs[r][kc+ii*4+0]=f2tf(qv.x); Qs[r][kc+ii*4+1]=f2tf(qv.y);
            Qs[r][kc+ii*4+2]=f2tf(qv.z); Qs[r][kc+ii*4+3]=f2tf(qv.w);
        }
    }
    if (tid < 64) { rowm[tid] = -1e30f; rowl[tid] = 0.f; }
    float o[2][2][4];
#pragma unroll
    for (int i=0;i<2;i++)
#pragma unroll
        for (int j=0;j<2;j++)
#pragma unroll
            for (int h=0;h<4;h++) o[i][j][h]=0.f;
    __syncthreads();

    for (int c0 = 0; c0 < chunk; c0 += 64) {
        {
            int r = tid >> 2, kc = (tid & 3) * 16;
#pragma unroll
            for (int ii = 0; ii < 4; ii++) {
                float4 kv = *(const float4*)&Kb[(size_t)(c0+r)*64 + kc + ii*4];
                Ks[r][kc+ii*4+0]=f2tf(kv.x); Ks[r][kc+ii*4+1]=f2tf(kv.y);
                Ks[r][kc+ii*4+2]=f2tf(kv.z); Ks[r][kc+ii*4+3]=f2tf(kv.w);
                float4 vv = *(const float4*)&Vb[(size_t)(c0+r)*64 + kc + ii*4];
                Vs[r][kc+ii*4+0]=f2tf(vv.x); Vs[r][kc+ii*4+1]=f2tf(vv.y);
                Vs[r][kc+ii*4+2]=f2tf(vv.z); Vs[r][kc+ii*4+3]=f2tf(vv.w);
            }
        }
        __syncthreads();

        float s[2][2][4];
#pragma unroll
        for (int i=0;i<2;i++)
#pragma unroll
            for (int j=0;j<2;j++)
#pragma unroll
                for (int h=0;h<4;h++) s[i][j][h]=0.f;
#pragma unroll
        for (int ks = 0; ks < 64; ks += 8) {
            uint32_t af[2][4], bf[2][2];
#pragma unroll
            for (int i = 0; i < 2; i++) {
                int r = wm*32 + i*16 + g;
                af[i][0] = __float_as_uint(Qs[r][ks+t4]);
                af[i][1] = __float_as_uint(Qs[r+8][ks+t4]);
                af[i][2] = __float_as_uint(Qs[r][ks+t4+4]);
                af[i][3] = __float_as_uint(Qs[r+8][ks+t4+4]);
            }
#pragma unroll
            for (int j = 0; j < 2; j++) {
                int cc = wn*16 + j*8 + g;
                bf[j][0] = __float_as_uint(Ks[cc][ks+t4]);
                bf[j][1] = __float_as_uint(Ks[cc][ks+t4+4]);
            }
#pragma unroll
            for (int i = 0; i < 2; i++)
#pragma unroll
                for (int j = 0; j < 2; j++) {
                    asm volatile(
                        "mma.sync.aligned.m16n8k8.row.col.f32.tf32.tf32.f32 "
                        "{%0,%1,%2,%3}, {%4,%5,%6,%7}, {%8,%9}, {%0,%1,%2,%3};\n"
                        : "+f"(s[i][j][0]), "+f"(s[i][j][1]),
                          "+f"(s[i][j][2]), "+f"(s[i][j][3])
                        : "r"(af[i][0]), "r"(af[i][1]), "r"(af[i][2]), "r"(af[i][3]),
                          "r"(bf[j][0]), "r"(bf[j][1]));
                }
        }

        float pm[2][2];
#pragma unroll
        for (int i=0;i<2;i++)
#pragma unroll
            for (int h=0;h<2;h++)
                pm[i][h] = fmaxf(fmaxf(s[i][0][2*h], s[i][0][2*h+1]),
                                 fmaxf(s[i][1][2*h], s[i][1][2*h+1]));
#pragma unroll
        for (int off = 1; off <= 2; off <<= 1) {
#pragma unroll
            for (int i=0;i<2;i++)
#pragma unroll
                for (int h=0;h<2;h++)
                    pm[i][h] = fmaxf(pm[i][h], __shfl_xor_sync(0xffffffffu, pm[i][h], off));
        }
        if (t4 == 0) {
#pragma unroll
            for (int i=0;i<2;i++)
#pragma unroll
                for (int h=0;h<2;h++)
                    redm[wm*32 + i*16 + g + h*8][wn] = pm[i][h];
        }
        __syncthreads();

        float mnew[2][2], scale[2][2];
#pragma unroll
        for (int i=0;i<2;i++)
#pragma unroll
            for (int h=0;h<2;h++) {
                int r = wm*32 + i*16 + g + h*8;
                float m = fmaxf(fmaxf(redm[r][0], redm[r][1]),
                                fmaxf(redm[r][2], redm[r][3]));
                float mo = rowm[r];
                mnew[i][h] = fmaxf(mo, m);
                scale[i][h] = __expf(mo - mnew[i][h]);
            }

        float psum[2][2] = {{0.f,0.f},{0.f,0.f}};
#pragma unroll
        for (int i=0;i<2;i++)
#pragma unroll
            for (int j=0;j<2;j++)
#pragma unroll
                for (int h=0;h<2;h++) {
                    int r = wm*32 + i*16 + g + h*8;
                    float p0 = __expf(s[i][j][2*h]   - mnew[i][h]);
                    float p1 = __expf(s[i][j][2*h+1] - mnew[i][h]);
                    *(float2*)&Ps[r][wn*16 + j*8 + 2*t4] = make_float2(f2tf(p0), f2tf(p1));
                    psum[i][h] += p0 + p1;
                    o[i][j][2*h]   *= scale[i][h];
                    o[i][j][2*h+1] *= scale[i][h];
                }
#pragma unroll
        for (int off = 1; off <= 2; off <<= 1) {
#pragma unroll
            for (int i=0;i<2;i++)
#pragma unroll
                for (int h=0;h<2;h++)
                    psum[i][h] += __shfl_xor_sync(0xffffffffu, psum[i][h], off);
        }
        if (t4 == 0) {
#pragma unroll
            for (int i=0;i<2;i++)
#pragma unroll
                for (int h=0;h<2;h++)
                    reds[wm*32 + i*16 + g + h*8][wn] = psum[i][h];
        }
        __syncthreads();

        if (wn == 0 && t4 == 0) {
#pragma unroll
            for (int i=0;i<2;i++)
#pragma unroll
                for (int h=0;h<2;h++) {
                    int r = wm*32 + i*16 + g + h*8;
                    float ps = reds[r][0] + reds[r][1] + reds[r][2] + reds[r][3];
                    rowl[r] = rowl[r]*scale[i][h] + ps;
                    rowm[r] = mnew[i][h];
                }
        }

#pragma unroll
        for (int ks = 0; ks < 64; ks += 8) {
            uint32_t af[2][4], bf[2][2];
#pragma unroll
            for (int i = 0; i < 2; i++) {
                int r = wm*32 + i*16 + g;
                af[i][0] = __float_as_uint(Ps[r][ks+t4]);
                af[i][1] = __float_as_uint(Ps[r+8][ks+t4]);
                af[i][2] = __float_as_uint(Ps[r][ks+t4+4]);
                af[i][3] = __float_as_uint(Ps[r+8][ks+t4+4]);
            }
#pragma unroll
            for (int j = 0; j < 2; j++) {
                int cc = wn*16 + j*8 + g;
                bf[j][0] = __float_as_uint(Vs[ks+t4][cc]);
                bf[j][1] = __float_as_uint(Vs[ks+t4+4][cc]);
            }
#pragma unroll
            for (int i = 0; i < 2; i++)
#pragma unroll
                for (int j = 0; j < 2; j++) {
                    asm volatile(
                        "mma.sync.aligned.m16n8k8.row.col.f32.tf32.tf32.f32 "
                        "{%0,%1,%2,%3}, {%4,%5,%6,%7}, {%8,%9}, {%0,%1,%2,%3};\n"
                        : "+f"(o[i][j][0]), "+f"(o[i][j][1]),
                          "+f"(o[i][j][2]), "+f"(o[i][j][3])
                        : "r"(af[i][0]), "r"(af[i][1]), "r"(af[i][2]), "r"(af[i][3]),
                          "r"(bf[j][0]), "r"(bf[j][1]));
                }
        }
        __syncthreads();
    }

    if (lpart != nullptr) {
        // split-K partial: un-divided O, plus m/l per row
        float* Ob = O + ((size_t)(blockIdx.z*32 + bh)*nq + q0) * 64;
#pragma unroll
        for (int i=0;i<2;i++)
#pragma unroll
            for (int j=0;j<2;j++)
#pragma unroll
                for (int h=0;h<2;h++) {
                    int r = wm*32 + i*16 + g + h*8;
                    int cc = wn*16 + j*8 + 2*t4;
                    *(float2*)&Ob[(size_t)r*64 + cc] =
                        make_float2(o[i][j][2*h], o[i][j][2*h+1]);
                }
        if (tid < 64) {
            size_t ri = (size_t)(blockIdx.z*32 + bh)*nq + q0 + tid;
            mpart[ri] = rowm[tid];
            lpart[ri] = rowl[tid];
        }
    } else {
        float* Ob = O + ((size_t)bh*nq + q0) * 64;
#pragma unroll
        for (int i=0;i<2;i++)
#pragma unroll
            for (int j=0;j<2;j++)
#pragma unroll
                for (int h=0;h<2;h++) {
                    int r = wm*32 + i*16 + g + h*8;
                    int cc = wn*16 + j*8 + 2*t4;
                    float inv = 1.f / rowl[r];
                    *(float2*)&Ob[(size_t)r*64 + cc] =
                        make_float2(o[i][j][2*h]*inv, o[i][j][2*h+1]*inv);
                }
    }
}

// ---------------------------------------------------------------------------
// Split-K combine: 4 partials -> w. Grid 8192 (bh*256+row), block 64 (cols).
// ---------------------------------------------------------------------------
__global__ void combine_kernel(const float* __restrict__ Op,
                               const float* __restrict__ mp,
                               const float* __restrict__ lp,
                               float* __restrict__ w) {
    int row = blockIdx.x;     // bh*256 + qr
    int c = threadIdx.x;
    int bh = row >> 8, qr = row & 255;
    float m0 = mp[(0*32+bh)*256+qr], m1 = mp[(1*32+bh)*256+qr];
    float m2 = mp[(2*32+bh)*256+qr], m3 = mp[(3*32+bh)*256+qr];
    float ms = fmaxf(fmaxf(m0,m1), fmaxf(m2,m3));
    float w0 = __expf(m0-ms), w1 = __expf(m1-ms), w2 = __expf(m2-ms), w3 = __expf(m3-ms);
    float l = w0*lp[(0*32+bh)*256+qr] + w1*lp[(1*32+bh)*256+qr]
            + w2*lp[(2*32+bh)*256+qr] + w3*lp[(3*32+bh)*256+qr];
    float acc = w0*Op[((size_t)(0*32+bh)*256+qr)*64 + c]
              + w1*Op[((size_t)(1*32+bh)*256+qr)*64 + c]
              + w2*Op[((size_t)(2*32+bh)*256+qr)*64 + c]
              + w3*Op[((size_t)(3*32+bh)*256+qr)*64 + c];
    w[((size_t)bh*256+qr)*64 + c] = acc / l;
}

// ---------------------------------------------------------------------------
// Depthwise seq-conv residual + layout transform
// ---------------------------------------------------------------------------
__global__ __launch_bounds__(256) void conv_kernel(
        const float* __restrict__ attn, const float* __restrict__ v,
        const float* __restrict__ cw, float* __restrict__ attn2) {
    __shared__ float vt[96][64];
    __shared__ float wk[33];
    int bh = blockIdx.y; int h = bh & 7; int b4 = bh >> 3;
    int row0 = blockIdx.x * 64;
    int t = threadIdx.x;
    if (t < 33) wk[t] = cw[h*33 + t];
    const float* vb = v + (size_t)bh*4096*64;
#pragma unroll
    for (int i=0;i<6;i++){
        int f = t + i*256;
        int r = f >> 4;
        int c4 = (f & 15) * 4;
        int gr = row0 - 16 + r;
        float4 val = make_float4(0.f,0.f,0.f,0.f);
        if (gr >= 0 && gr < 4096) val = *(const float4*)&vb[(size_t)gr*64 + c4];
        *(float4*)&vt[r][c4] = val;
    }
    __syncthreads();
    int dh = t & 63;
    int rr = t >> 6;
#pragma unroll
    for (int q=0;q<16;q++){
        int lr = rr + q*4;
        float acc = attn[((size_t)bh*4096 + row0 + lr)*64 + dh];
#pragma unroll
        for (int s=0;s<33;s++) acc += wk[s]*vt[lr+s][dh];
        attn2[((size_t)b4*4096 + row0 + lr)*512 + h*64 + dh] = acc;
    }
}

// ---------------------------------------------------------------------------
// Host orchestration
// ---------------------------------------------------------------------------
extern "C" void kernel_launch(void* const* d_in, const int* in_sizes, int n_in,
                              void* d_out, int out_size) {
    const float* x      = (const float*)d_in[0];
    const float* norm_w = (const float*)d_in[1];
    const float* norm_b = (const float*)d_in[2];
    const float* Wqkv   = (const float*)d_in[3];
    const float* Wout   = (const float*)d_in[4];
    const float* bout   = (const float*)d_in[5];
    const float* conv_w = (const float*)d_in[6];
    float* out = (float*)d_out;

    float *xn,*q,*k,*v,*ql,*kl,*a2,*z0,*z1,*t1,*t2,*t3,*w,*w2,*attn,*attn2,*red;
    cudaGetSymbolAddress((void**)&xn,   g_xn);
    cudaGetSymbolAddress((void**)&q,    g_q);
    cudaGetSymbolAddress((void**)&k,    g_k);
    cudaGetSymbolAddress((void**)&v,    g_v);
    cudaGetSymbolAddress((void**)&ql,   g_ql);
    cudaGetSymbolAddress((void**)&kl,   g_kl);
    cudaGetSymbolAddress((void**)&a2,   g_a2);
    cudaGetSymbolAddress((void**)&z0,   g_z0);
    cudaGetSymbolAddress((void**)&z1,   g_z1);
    cudaGetSymbolAddress((void**)&t1,   g_t1);
    cudaGetSymbolAddress((void**)&t2,   g_t2);
    cudaGetSymbolAddress((void**)&t3,   g_t3);
    cudaGetSymbolAddress((void**)&w,    g_w);
    cudaGetSymbolAddress((void**)&w2,   g_w2);
    cudaGetSymbolAddress((void**)&attn, g_attn);
    cudaGetSymbolAddress((void**)&attn2,g_attn2);
    cudaGetSymbolAddress((void**)&red,  g_red);

    cudaFuncSetAttribute(flash_tc_kernel, cudaFuncAttributeMaxDynamicSharedMemorySize, SMEM_FLASH_TC);
    cudaFuncSetAttribute(a2_tc_kernel, cudaFuncAttributeMaxDynamicSharedMemorySize, SMEM_A2);

    // 1. LayerNorm
    ln_kernel<<<16384, 128>>>(x, norm_w, norm_b, xn);
    // 2. QKV projection (tf32 MMA, fused scatter + q scale)
    mma_gemm<0,512,1536,512><<<dim3(12,128), 256>>>(
        xn, Wqkv, q, k, v, nullptr, nullptr);
    // 3. landmarks (merged)
    landmark2_kernel<<<4096, 256>>>(q, k, ql, kl);
    // 4. a2 = softmax(q_l k_l^T) (tf32 MMA)
    a2_tc_kernel<<<dim3(2,32), 256, SMEM_A2>>>(ql, kl, a2);
    // 5. pinv init scalar (col-sum max; row-sum max == 1 exactly)
    red_init_kernel<<<1, 32>>>(red);
    colsum_kernel<<<32, 256>>>(a2, red);
    zinit_kernel<<<8192, 256>>>(a2, red, z0);
    // 6. w = softmax(q_l k^T) @ v — split-K x4 flash + combine
    flash_tc_kernel<<<dim3(4,32,4), 256, SMEM_FLASH_TC>>>(
        ql, k, v, t1, 256, 4096, 1024, t2, t2 + 32768);
    combine_kernel<<<8192, 64>>>(t1, t2, t2 + 32768, w);
    // 7. Newton-Schulz pinv (tf32 MMA, fused epilogues) — t1..t3 free again
    float* zin = z0; float* zout = z1;
    for (int it = 0; it < 6; it++) {
        mma_gemm_pinv<<<dim3(2,2,32), 256>>>(a2, zin, t1, 0.f,   1.f);
        mma_gemm_pinv<<<dim3(2,2,32), 256>>>(t1, t1, t2, 7.f,   -1.f);
        mma_gemm_pinv<<<dim3(2,2,32), 256>>>(t1, t2, t3, 15.f,  -1.f);
        mma_gemm_pinv<<<dim3(2,2,32), 256>>>(zin, t3, zout, 3.25f, -0.25f);
        float* tmp = zin; zin = zout; zout = tmp;
    }
    // 8. w2 = pinv(a2) @ w (tf32 MMA)
    mma_w2_kernel<<<dim3(1,2,32), 256>>>(zin, w, w2);
    // 9. attn = softmax(q k_l^T) @ w2 (tf32 flash, no split)
    flash_tc_kernel<<<dim3(64,32,1), 256, SMEM_FLASH_TC>>>(
        q, kl, w2, attn, 4096, 256, 256, nullptr, nullptr);
    // 10. conv residual + layout
    conv_kernel<<<dim3(64,32), 256>>>(attn, v, conv_w, attn2);
    // 11. output projection + bias + input residual (tf32 MMA)
    mma_gemm<1,512,512,512><<<dim3(4,128), 256>>>(
        attn2, Wout, out, nullptr, nullptr, bout, x);
}